// round 1
// baseline (speedup 1.0000x reference)
#include <cuda_runtime.h>

// out[b,d,k] = sum_e S[k,d,e] * (x[b,e,k] - mu[e,k])
// B=8192, D=E=64, K=128. All fp32.
// Strategy: per-CTA k-tile of 8, S tile staged in SMEM swizzled for packed
// f32x2 FMAs; mu folded into a precomputed constant c = S@mu.

using ull = unsigned long long;

#define NBY 18   // b-slices in grid.y (288 CTAs total)

__device__ __forceinline__ void ffma2(ull &d, ull a, ull b) {
    // packed dual fp32 FMA (sm_100+): d.{lo,hi} += a.{lo,hi} * b.{lo,hi}
    asm("fma.rn.f32x2 %0, %1, %2, %0;" : "+l"(d) : "l"(a), "l"(b));
}

__global__ __launch_bounds__(256, 1)
void cluster_norm_kernel(const float* __restrict__ x,
                         const float* __restrict__ mu,
                         const float* __restrict__ S,
                         float* __restrict__ out)
{
    extern __shared__ float smem_f[];
    float* Sf = smem_f;           // 32768 floats = 128KB swizzled S tile
    float* Cf = smem_f + 32768;   // 512 floats   = -c[d,k] for this k-tile

    const int tid   = threadIdx.x;
    const int kt    = blockIdx.x;       // 0..15 k-tile
    const int kbase = kt * 8;

    // ---- Stage S tile: S[kbase+kl][d][e], kl in 0..7 -> swizzled SMEM ----
    // Dest float index: e*512 + (d>>1)*16 + (kl>>1)*4 + (d&1)*2 + (kl&1)
    // so one float4 slot holds (d0k0, d0k1, d1k0, d1k1) for a (d-pair, k-pair).
    for (int g = tid; g < 8192; g += 256) {
        int kl = g >> 10;           // 0..7
        int d  = (g >> 4) & 63;     // 0..63
        int e4 = g & 15;            // 0..15 (float4 along e)
        const float4 v = *(const float4*)(S + (size_t)(kbase + kl) * 4096 + d * 64 + e4 * 4);
        int base = (d >> 1) * 16 + (kl >> 1) * 4 + (d & 1) * 2 + (kl & 1);
        int e0 = e4 * 4;
        Sf[(e0 + 0) * 512 + base] = v.x;
        Sf[(e0 + 1) * 512 + base] = v.y;
        Sf[(e0 + 2) * 512 + base] = v.z;
        Sf[(e0 + 3) * 512 + base] = v.w;
    }
    __syncthreads();

    // ---- Precompute -c[d,k] = -sum_e S[k,d,e]*mu[e,k] (per k-tile) ----
    if (tid < 128) {
        int kp = tid & 3, dp = tid >> 2;
        int k0 = kbase + kp * 2;
        float4 c = make_float4(0.f, 0.f, 0.f, 0.f);
        const float4* S4 = (const float4*)Sf;
        #pragma unroll 4
        for (int e = 0; e < 64; e++) {
            float4 sv = S4[e * 128 + dp * 4 + kp];
            float m0 = mu[e * 128 + k0];
            float m1 = mu[e * 128 + k0 + 1];
            c.x -= sv.x * m0;
            c.y -= sv.y * m1;
            c.z -= sv.z * m0;
            c.w -= sv.w * m1;
        }
        ((float4*)Cf)[tid] = c;
    }
    __syncthreads();

    const int kp = tid & 3;     // k-pair within tile
    const int bl = tid >> 2;    // 0..63 b within b-tile
    const int k0 = kbase + kp * 2;
    const ulonglong2* S2 = (const ulonglong2*)Sf;
    const ulonglong2* C2 = (const ulonglong2*)Cf;

    for (int bt = blockIdx.y; bt < 128; bt += NBY) {
        const int b = bt * 64 + bl;
        const float* xb = x   + (size_t)b * 64 * 128 + k0;
        float*       ob = out + (size_t)b * 64 * 128 + k0;

        // accumulators: acc[d] packs (k0,k1); init to -c
        ull acc[64];
        #pragma unroll
        for (int dp = 0; dp < 32; dp++) {
            ulonglong2 cc = C2[dp * 4 + kp];
            acc[2 * dp]     = cc.x;
            acc[2 * dp + 1] = cc.y;
        }

        // e-loop, prefetch depth 2 on the strided x stream
        ull xva = *(const ull*)(xb);
        ull xvb = *(const ull*)(xb + 128);
        for (int e = 0; e < 64; e++) {
            int ep = e + 2 < 63 ? e + 2 : 63;
            ull xnc = *(const ull*)(xb + ep * 128);
            const ulonglong2* sp = S2 + e * 128 + kp;
            #pragma unroll
            for (int dp = 0; dp < 32; dp++) {
                ulonglong2 s = sp[dp * 4];     // LDS.128: (d0k0,d0k1,d1k0,d1k1)
                ffma2(acc[2 * dp],     s.x, xva);
                ffma2(acc[2 * dp + 1], s.y, xva);
            }
            xva = xvb;
            xvb = xnc;
        }

        #pragma unroll
        for (int d = 0; d < 64; d++) {
            *(ull*)(ob + d * 128) = acc[d];    // STG.64, 8 x 32B sectors/warp
        }
    }
}

extern "C" void kernel_launch(void* const* d_in, const int* in_sizes, int n_in,
                              void* d_out, int out_size)
{
    const float* x  = (const float*)d_in[0];   // [8192, 64, 128]
    const float* mu = (const float*)d_in[1];   // [64, 128]
    const float* S  = (const float*)d_in[2];   // [128, 64, 64]
    float* out      = (float*)d_out;           // [8192, 64, 128]

    const int smem_bytes = (32768 + 512) * sizeof(float);  // 133120
    cudaFuncSetAttribute(cluster_norm_kernel,
                         cudaFuncAttributeMaxDynamicSharedMemorySize, smem_bytes);

    dim3 grid(16, NBY);
    cluster_norm_kernel<<<grid, 256, smem_bytes>>>(x, mu, S, out);
}

// round 2
// speedup vs baseline: 2.3733x; 2.3733x over previous
#include <cuda_runtime.h>

// out[b,d,k] = sum_e S[k,d,e] * (x[b,e,k] - mu[e,k])
// B=8192, D=E=64, K=128. fp32.
// R2: fix R1 register spills (254 regs -> local-mem thrash).
//   Thread tile: 16 d x 2 packed k x 2 b  -> 32 ull accs (64 regs).
//   512 threads/CTA (16 warps/SM), k-tile 8, S swizzled in SMEM for
//   broadcast-friendly LDS.128 + packed f32x2 FMAs. mu folded into -c = -S@mu.

using ull = unsigned long long;

#define NBY 9   // 16 x 9 = 144 CTAs (~1 wave on 148 SMs)

__device__ __forceinline__ void ffma2(ull &d, ull a, ull b) {
    asm("fma.rn.f32x2 %0, %1, %2, %0;" : "+l"(d) : "l"(a), "l"(b));
}

__global__ __launch_bounds__(512, 1)
void cluster_norm_kernel(const float* __restrict__ x,
                         const float* __restrict__ mu,
                         const float* __restrict__ S,
                         float* __restrict__ out)
{
    extern __shared__ float smem_f[];
    float* Sf = smem_f;           // 32768 floats = 128KB swizzled S tile
    float* Cf = smem_f + 32768;   // 512 floats   = -c for this k-tile

    const int tid   = threadIdx.x;
    const int kt    = blockIdx.x;       // 0..15
    const int kbase = kt * 8;

    // ---- Stage S tile: S[kbase+kl][d][e] -> swizzled SMEM ----
    // float index: e*512 + (d>>1)*16 + (kl>>1)*4 + (d&1)*2 + (kl&1)
    // one float4 slot = (d0k0, d0k1, d1k0, d1k1) for a (d-pair, k-pair).
    for (int g = tid; g < 8192; g += 512) {
        int kl = g >> 10;
        int d  = (g >> 4) & 63;
        int e4 = g & 15;
        const float4 v = *(const float4*)(S + (size_t)(kbase + kl) * 4096 + d * 64 + e4 * 4);
        int base = (d >> 1) * 16 + (kl >> 1) * 4 + (d & 1) * 2 + (kl & 1);
        int e0 = e4 * 4;
        Sf[(e0 + 0) * 512 + base] = v.x;
        Sf[(e0 + 1) * 512 + base] = v.y;
        Sf[(e0 + 2) * 512 + base] = v.z;
        Sf[(e0 + 3) * 512 + base] = v.w;
    }
    __syncthreads();

    // ---- -c[d,kpair] = -sum_e S[k,d,e]*mu[e,k] ----
    if (tid < 128) {
        int kp = tid & 3, dp = tid >> 2;
        int k0 = kbase + kp * 2;
        float4 c = make_float4(0.f, 0.f, 0.f, 0.f);
        const float4* S4 = (const float4*)Sf;
        #pragma unroll 4
        for (int e = 0; e < 64; e++) {
            float4 sv = S4[e * 128 + dp * 4 + kp];
            float m0 = mu[e * 128 + k0];
            float m1 = mu[e * 128 + k0 + 1];
            c.x -= sv.x * m0;
            c.y -= sv.y * m1;
            c.z -= sv.z * m0;
            c.w -= sv.w * m1;
        }
        ((float4*)Cf)[tid] = c;
    }
    __syncthreads();

    // Thread decomposition (512 threads):
    //   kp    = tid & 3          k-pair (warp lanes 0-3)
    //   blLow = (tid>>2) & 7     b within warp (8 lanes broadcast S)
    //   dg    = (tid>>5) & 3     d-group of 16 (warp id low bits)
    //   blHi  = tid >> 7         (0..3)
    const int kp    = tid & 3;
    const int bl    = ((tid >> 7) << 3) | ((tid >> 2) & 7);  // 0..31
    const int dg    = (tid >> 5) & 3;
    const int k0    = kbase + kp * 2;

    const ulonglong2* S2 = (const ulonglong2*)Sf;
    const ulonglong2* C2 = (const ulonglong2*)Cf;
    const int sOff = dg * 32 + kp;           // + e*128 + j*4

    for (int bt = blockIdx.y; bt < 128; bt += NBY) {
        const int b0 = bt * 64 + bl;         // second b is b0 + 32
        const float* xp0 = x + (size_t)b0 * 8192 + k0;
        const float* xp1 = xp0 + 32 * 8192;

        // acc[b][j*2 + {0,1}] : d = dg*16 + j*2 + {0,1}, packed (k0,k1)
        ull acc0[16], acc1[16];
        #pragma unroll
        for (int j = 0; j < 8; j++) {
            ulonglong2 cc = C2[(dg * 8 + j) * 4 + kp];
            acc0[2*j] = cc.x;  acc0[2*j+1] = cc.y;
            acc1[2*j] = cc.x;  acc1[2*j+1] = cc.y;
        }

        // e-loop with depth-2 prefetch on both b streams
        ull x0a = *(const ull*)(xp0);
        ull x1a = *(const ull*)(xp1);
        ull x0b = *(const ull*)(xp0 + 128);
        ull x1b = *(const ull*)(xp1 + 128);
        for (int e = 0; e < 64; e++) {
            const int ep = (e + 2 < 63 ? e + 2 : 63) * 128;
            ull x0n = *(const ull*)(xp0 + ep);
            ull x1n = *(const ull*)(xp1 + ep);
            const ulonglong2* sp = S2 + e * 128 + sOff;
            #pragma unroll
            for (int j = 0; j < 8; j++) {
                ulonglong2 s = sp[j * 4];      // 64B/warp unique, broadcast x8
                ffma2(acc0[2*j],   s.x, x0a);
                ffma2(acc0[2*j+1], s.y, x0a);
                ffma2(acc1[2*j],   s.x, x1a);
                ffma2(acc1[2*j+1], s.y, x1a);
            }
            x0a = x0b; x1a = x1b;
            x0b = x0n; x1b = x1n;
        }

        float* op0 = out + (size_t)b0 * 8192 + k0;
        float* op1 = op0 + 32 * 8192;
        #pragma unroll
        for (int j = 0; j < 8; j++) {
            const int d0 = dg * 16 + j * 2;
            *(ull*)(op0 + (size_t)d0 * 128)       = acc0[2*j];
            *(ull*)(op0 + (size_t)(d0+1) * 128)   = acc0[2*j+1];
            *(ull*)(op1 + (size_t)d0 * 128)       = acc1[2*j];
            *(ull*)(op1 + (size_t)(d0+1) * 128)   = acc1[2*j+1];
        }
    }
}

extern "C" void kernel_launch(void* const* d_in, const int* in_sizes, int n_in,
                              void* d_out, int out_size)
{
    const float* x  = (const float*)d_in[0];   // [8192, 64, 128]
    const float* mu = (const float*)d_in[1];   // [64, 128]
    const float* S  = (const float*)d_in[2];   // [128, 64, 64]
    float* out      = (float*)d_out;           // [8192, 64, 128]

    const int smem_bytes = (32768 + 512) * sizeof(float);  // 133120
    cudaFuncSetAttribute(cluster_norm_kernel,
                         cudaFuncAttributeMaxDynamicSharedMemorySize, smem_bytes);

    dim3 grid(16, NBY);
    cluster_norm_kernel<<<grid, 512, smem_bytes>>>(x, mu, S, out);
}

// round 3
// speedup vs baseline: 2.4162x; 1.0181x over previous
#include <cuda_runtime.h>

// out[b,d,k] = sum_e S[k,d,e] * (x[b,e,k] - mu[e,k])
// B=8192, D=E=64, K=128. fp32.
// R2: fix R1 register spills (254 regs -> local-mem thrash).
//   Thread tile: 16 d x 2 packed k x 2 b  -> 32 ull accs (64 regs).
//   512 threads/CTA (16 warps/SM), k-tile 8, S swizzled in SMEM for
//   broadcast-friendly LDS.128 + packed f32x2 FMAs. mu folded into -c = -S@mu.

using ull = unsigned long long;

#define NBY 9   // 16 x 9 = 144 CTAs (~1 wave on 148 SMs)

__device__ __forceinline__ void ffma2(ull &d, ull a, ull b) {
    asm("fma.rn.f32x2 %0, %1, %2, %0;" : "+l"(d) : "l"(a), "l"(b));
}

__global__ __launch_bounds__(512, 1)
void cluster_norm_kernel(const float* __restrict__ x,
                         const float* __restrict__ mu,
                         const float* __restrict__ S,
                         float* __restrict__ out)
{
    extern __shared__ float smem_f[];
    float* Sf = smem_f;           // 32768 floats = 128KB swizzled S tile
    float* Cf = smem_f + 32768;   // 512 floats   = -c for this k-tile

    const int tid   = threadIdx.x;
    const int kt    = blockIdx.x;       // 0..15
    const int kbase = kt * 8;

    // ---- Stage S tile: S[kbase+kl][d][e] -> swizzled SMEM ----
    // float index: e*512 + (d>>1)*16 + (kl>>1)*4 + (d&1)*2 + (kl&1)
    // one float4 slot = (d0k0, d0k1, d1k0, d1k1) for a (d-pair, k-pair).
    for (int g = tid; g < 8192; g += 512) {
        int kl = g >> 10;
        int d  = (g >> 4) & 63;
        int e4 = g & 15;
        const float4 v = *(const float4*)(S + (size_t)(kbase + kl) * 4096 + d * 64 + e4 * 4);
        int base = (d >> 1) * 16 + (kl >> 1) * 4 + (d & 1) * 2 + (kl & 1);
        int e0 = e4 * 4;
        Sf[(e0 + 0) * 512 + base] = v.x;
        Sf[(e0 + 1) * 512 + base] = v.y;
        Sf[(e0 + 2) * 512 + base] = v.z;
        Sf[(e0 + 3) * 512 + base] = v.w;
    }
    __syncthreads();

    // ---- -c[d,kpair] = -sum_e S[k,d,e]*mu[e,k] ----
    if (tid < 128) {
        int kp = tid & 3, dp = tid >> 2;
        int k0 = kbase + kp * 2;
        float4 c = make_float4(0.f, 0.f, 0.f, 0.f);
        const float4* S4 = (const float4*)Sf;
        #pragma unroll 4
        for (int e = 0; e < 64; e++) {
            float4 sv = S4[e * 128 + dp * 4 + kp];
            float m0 = mu[e * 128 + k0];
            float m1 = mu[e * 128 + k0 + 1];
            c.x -= sv.x * m0;
            c.y -= sv.y * m1;
            c.z -= sv.z * m0;
            c.w -= sv.w * m1;
        }
        ((float4*)Cf)[tid] = c;
    }
    __syncthreads();

    // Thread decomposition (512 threads):
    //   kp    = tid & 3          k-pair (warp lanes 0-3)
    //   blLow = (tid>>2) & 7     b within warp (8 lanes broadcast S)
    //   dg    = (tid>>5) & 3     d-group of 16 (warp id low bits)
    //   blHi  = tid >> 7         (0..3)
    const int kp    = tid & 3;
    const int bl    = ((tid >> 7) << 3) | ((tid >> 2) & 7);  // 0..31
    const int dg    = (tid >> 5) & 3;
    const int k0    = kbase + kp * 2;

    const ulonglong2* S2 = (const ulonglong2*)Sf;
    const ulonglong2* C2 = (const ulonglong2*)Cf;
    const int sOff = dg * 32 + kp;           // + e*128 + j*4

    for (int bt = blockIdx.y; bt < 128; bt += NBY) {
        const int b0 = bt * 64 + bl;         // second b is b0 + 32
        const float* xp0 = x + (size_t)b0 * 8192 + k0;
        const float* xp1 = xp0 + 32 * 8192;

        // acc[b][j*2 + {0,1}] : d = dg*16 + j*2 + {0,1}, packed (k0,k1)
        ull acc0[16], acc1[16];
        #pragma unroll
        for (int j = 0; j < 8; j++) {
            ulonglong2 cc = C2[(dg * 8 + j) * 4 + kp];
            acc0[2*j] = cc.x;  acc0[2*j+1] = cc.y;
            acc1[2*j] = cc.x;  acc1[2*j+1] = cc.y;
        }

        // e-loop with depth-2 prefetch on both b streams
        ull x0a = *(const ull*)(xp0);
        ull x1a = *(const ull*)(xp1);
        ull x0b = *(const ull*)(xp0 + 128);
        ull x1b = *(const ull*)(xp1 + 128);
        for (int e = 0; e < 64; e++) {
            const int ep = (e + 2 < 63 ? e + 2 : 63) * 128;
            ull x0n = *(const ull*)(xp0 + ep);
            ull x1n = *(const ull*)(xp1 + ep);
            const ulonglong2* sp = S2 + e * 128 + sOff;
            #pragma unroll
            for (int j = 0; j < 8; j++) {
                ulonglong2 s = sp[j * 4];      // 64B/warp unique, broadcast x8
                ffma2(acc0[2*j],   s.x, x0a);
                ffma2(acc0[2*j+1], s.y, x0a);
                ffma2(acc1[2*j],   s.x, x1a);
                ffma2(acc1[2*j+1], s.y, x1a);
            }
            x0a = x0b; x1a = x1b;
            x0b = x0n; x1b = x1n;
        }

        float* op0 = out + (size_t)b0 * 8192 + k0;
        float* op1 = op0 + 32 * 8192;
        #pragma unroll
        for (int j = 0; j < 8; j++) {
            const int d0 = dg * 16 + j * 2;
            *(ull*)(op0 + (size_t)d0 * 128)       = acc0[2*j];
            *(ull*)(op0 + (size_t)(d0+1) * 128)   = acc0[2*j+1];
            *(ull*)(op1 + (size_t)d0 * 128)       = acc1[2*j];
            *(ull*)(op1 + (size_t)(d0+1) * 128)   = acc1[2*j+1];
        }
    }
}

extern "C" void kernel_launch(void* const* d_in, const int* in_sizes, int n_in,
                              void* d_out, int out_size)
{
    const float* x  = (const float*)d_in[0];   // [8192, 64, 128]
    const float* mu = (const float*)d_in[1];   // [64, 128]
    const float* S  = (const float*)d_in[2];   // [128, 64, 64]
    float* out      = (float*)d_out;           // [8192, 64, 128]

    const int smem_bytes = (32768 + 512) * sizeof(float);  // 133120
    cudaFuncSetAttribute(cluster_norm_kernel,
                         cudaFuncAttributeMaxDynamicSharedMemorySize, smem_bytes);

    dim3 grid(16, NBY);
    cluster_norm_kernel<<<grid, 512, smem_bytes>>>(x, mu, S, out);
}

// round 4
// speedup vs baseline: 2.7659x; 1.1447x over previous
#include <cuda_runtime.h>
#include <cstdint>

// out[b,d,k] = sum_e S[k,d,e] * (x[b,e,k] - mu[e,k])
// B=8192, D=E=64, K=128. fp32.
// R4: fix R3 L1-wavefront bound.
//  - 256 threads (reg ceiling 255 -> no spills), tile 16d x 2k-packed x 2b.
//  - x staged in SMEM via cp.async (double-buffered 32-e halves) so the
//    compute loop does 1 conflict-free LDS.128 for x instead of scattered LDG.
//  - S (128KB) swizzled in SMEM, mu folded into -c = -S@mu.

using ull = unsigned long long;

#define NBY 9            // 16 k-tiles x 9 = 144 CTAs (~1 wave)
#define NBT 256          // 8192 / 32 b per tile

__device__ __forceinline__ void ffma2(ull &d, ull a, ull b) {
    asm("fma.rn.f32x2 %0, %1, %2, %0;" : "+l"(d) : "l"(a), "l"(b));
}
__device__ __forceinline__ void cpa8(uint32_t dst, const float* src) {
    asm volatile("cp.async.ca.shared.global [%0], [%1], 8;" :: "r"(dst), "l"(src));
}
__device__ __forceinline__ void cpa_commit() {
    asm volatile("cp.async.commit_group;");
}
__device__ __forceinline__ void cpa_wait1() {
    asm volatile("cp.async.wait_group 1;");
}

__global__ __launch_bounds__(256, 1)
void cluster_norm_kernel(const float* __restrict__ x,
                         const float* __restrict__ mu,
                         const float* __restrict__ S,
                         float* __restrict__ out)
{
    extern __shared__ float smem_f[];
    float* Sf = smem_f;            // 32768 floats : swizzled S tile (128KB)
    float* Cf = smem_f + 32768;    // 512 floats   : -c[d,kpair]
    float* Xf = smem_f + 33280;    // 2 x 8192 floats : x half-tile double buffer

    const int tid   = threadIdx.x;
    const int kt    = blockIdx.x;       // 0..15
    const int kbase = kt * 8;
    const int by    = blockIdx.y;

    // ---- Stage S tile: S[kbase+kl][d][e] -> swizzled SMEM ----
    // float idx: e*512 + (d>>1)*16 + (kl>>1)*4 + (d&1)*2 + (kl&1)
    for (int g = tid; g < 8192; g += 256) {
        int kl = g >> 10;
        int d  = (g >> 4) & 63;
        int e4 = g & 15;
        const float4 v = *(const float4*)(S + (size_t)(kbase + kl) * 4096 + d * 64 + e4 * 4);
        int base = (d >> 1) * 16 + (kl >> 1) * 4 + (d & 1) * 2 + (kl & 1);
        int e0 = e4 * 4;
        Sf[(e0 + 0) * 512 + base] = v.x;
        Sf[(e0 + 1) * 512 + base] = v.y;
        Sf[(e0 + 2) * 512 + base] = v.z;
        Sf[(e0 + 3) * 512 + base] = v.w;
    }
    __syncthreads();

    // ---- -c[d,kpair] = -sum_e S[k,d,e]*mu[e,k] ----
    if (tid < 128) {
        int kp = tid & 3, dp = tid >> 2;
        int k0c = kbase + kp * 2;
        float4 c = make_float4(0.f, 0.f, 0.f, 0.f);
        const float4* S4 = (const float4*)Sf;
        #pragma unroll 4
        for (int e = 0; e < 64; e++) {
            float4 sv = S4[e * 128 + dp * 4 + kp];
            float m0 = mu[e * 128 + k0c];
            float m1 = mu[e * 128 + k0c + 1];
            c.x -= sv.x * m0;
            c.y -= sv.y * m1;
            c.z -= sv.z * m0;
            c.w -= sv.w * m1;
        }
        ((float4*)Cf)[tid] = c;
    }
    __syncthreads();

    // Thread decomposition: kp = tid&3, blLow = (tid>>2)&7,
    // warp w = tid>>5: dg = w&3 (d-group of 16), blHi = w>>2.
    const int kp = tid & 3;
    const int dg = (tid >> 5) & 3;
    const int bl = (((tid >> 7) & 1) << 3) | ((tid >> 2) & 7);  // 0..15
    const int k0 = kbase + kp * 2;

    const ulonglong2* S2 = (const ulonglong2*)Sf;
    const ulonglong2* C2 = (const ulonglong2*)Cf;

    // cp.async half-tile loader: 8192 floats = 4096 x 8B ops, 16 per thread.
    // op o: kp_o=o&3, e2=(o>>2)&31, bl_o=(o>>7)&15, bsel=(o>>11)&1
    // smem float idx: e2*256 + bl_o*16 + kp_o*4 + bsel*2
    auto load_half = [&](int buf, int bt, int eh) {
        uint32_t xsh = (uint32_t)__cvta_generic_to_shared(Xf + buf * 8192);
        #pragma unroll
        for (int i = 0; i < 16; i++) {
            int o    = tid + 256 * i;
            int kpo  = o & 3;
            int e2   = (o >> 2) & 31;
            int blo  = (o >> 7) & 15;
            int bs   = (o >> 11) & 1;
            int b    = bt * 32 + blo + bs * 16;
            int e    = eh * 32 + e2;
            const float* src = x + (size_t)b * 8192 + (size_t)e * 128 + kbase + kpo * 2;
            uint32_t dst = xsh + (uint32_t)(e2 * 256 + blo * 16 + kpo * 4 + bs * 2) * 4u;
            cpa8(dst, src);
        }
        cpa_commit();
    };

    // Pipeline state: (lb, lh) = next half to load; clamp when past the end.
    int lb = by, lh = 0;
    auto advance = [&]() {
        lh ^= 1;
        if (lh == 0) { lb += NBY; if (lb >= NBT) lb = by; }
    };

    load_half(0, lb, lh);   // prologue: (by, 0) into buf 0
    advance();
    int cur = 0;

    for (int bt = by; bt < NBT; bt += NBY) {
        const int b0 = bt * 32 + bl;        // second b is b0 + 16

        // init accumulators to -c
        ull acc0[16], acc1[16];
        #pragma unroll
        for (int j = 0; j < 8; j++) {
            ulonglong2 cc = C2[(dg * 8 + j) * 4 + kp];
            acc0[2*j] = cc.x;  acc0[2*j+1] = cc.y;
            acc1[2*j] = cc.x;  acc1[2*j+1] = cc.y;
        }

        #pragma unroll
        for (int h = 0; h < 2; h++) {
            load_half(cur ^ 1, lb, lh);     // issue next half
            advance();
            cpa_wait1();                    // current half (issued last iter) done
            __syncthreads();

            const ulonglong2* xb = (const ulonglong2*)(Xf + cur * 8192) + bl * 4 + kp;
            const ulonglong2* sp0 = S2 + (h * 32) * 128 + dg * 32 + kp;
            #pragma unroll 2
            for (int e2 = 0; e2 < 32; e2++) {
                ulonglong2 xv = xb[e2 * 64];          // (x_b0 kpair, x_b1 kpair)
                const ulonglong2* sp = sp0 + e2 * 128;
                #pragma unroll
                for (int j = 0; j < 8; j++) {
                    ulonglong2 s = sp[j * 4];         // 64B/warp, broadcast x8
                    ffma2(acc0[2*j],   s.x, xv.x);
                    ffma2(acc0[2*j+1], s.y, xv.x);
                    ffma2(acc1[2*j],   s.x, xv.y);
                    ffma2(acc1[2*j+1], s.y, xv.y);
                }
            }
            __syncthreads();                // all readers done before buf reuse
            cur ^= 1;
        }

        float* op0 = out + (size_t)b0 * 8192 + k0;
        float* op1 = op0 + (size_t)16 * 8192;
        #pragma unroll
        for (int j = 0; j < 8; j++) {
            const int d0 = dg * 16 + j * 2;
            *(ull*)(op0 + (size_t)d0 * 128)     = acc0[2*j];
            *(ull*)(op0 + (size_t)(d0+1) * 128) = acc0[2*j+1];
            *(ull*)(op1 + (size_t)d0 * 128)     = acc1[2*j];
            *(ull*)(op1 + (size_t)(d0+1) * 128) = acc1[2*j+1];
        }
    }
}

extern "C" void kernel_launch(void* const* d_in, const int* in_sizes, int n_in,
                              void* d_out, int out_size)
{
    const float* x  = (const float*)d_in[0];   // [8192, 64, 128]
    const float* mu = (const float*)d_in[1];   // [64, 128]
    const float* S  = (const float*)d_in[2];   // [128, 64, 64]
    float* out      = (float*)d_out;           // [8192, 64, 128]

    const int smem_bytes = (32768 + 512 + 2 * 8192) * sizeof(float);  // 198656
    cudaFuncSetAttribute(cluster_norm_kernel,
                         cudaFuncAttributeMaxDynamicSharedMemorySize, smem_bytes);

    dim3 grid(16, NBY);
    cluster_norm_kernel<<<grid, 256, smem_bytes>>>(x, mu, S, out);
}